// round 1
// baseline (speedup 1.0000x reference)
#include <cuda_runtime.h>
#include <math.h>

#define BDIM 8
#define CDIM 320
#define T0   2048
#define NLEV 12
#define NDIV 11.0

// Pyramid scratch for levels 1..11: sum(T_k, k=1..11) = 2047
__device__ float g_p1[BDIM * CDIM * 2047];
__device__ float g_p2[BDIM * CDIM * 2047];

// Per-level accumulators (double for deterministic-enough accumulation)
__device__ double g_lse_i[NLEV], g_pos_i[NLEV], g_lse_t[NLEV], g_pos_t[NLEV];

__global__ void init_acc() {
    int i = threadIdx.x;
    if (i < NLEV) {
        g_lse_i[i] = 0.0; g_pos_i[i] = 0.0;
        g_lse_t[i] = 0.0; g_pos_t[i] = 0.0;
    }
}

// max-pool1d kernel=2 stride=2 along T. in: [B*C, Tin], out: [B*C, Tin/2]
__global__ void pool_kernel(const float* __restrict__ in, float* __restrict__ out, int Tin) {
    int Tout = Tin >> 1;
    int n = BDIM * CDIM * Tout;
    for (int i = blockIdx.x * blockDim.x + threadIdx.x; i < n; i += gridDim.x * blockDim.x) {
        int bc = i / Tout;
        int t  = i - bc * Tout;
        const float* p = in + bc * Tin + 2 * t;
        out[i] = fmaxf(p[0], p[1]);
    }
}

// ---------------- instance contrast: N=8 (batch), L=T ----------------
// one block per l (= t index). 16x16 sim from 16 vectors of length 320.
__global__ void inst_kernel(const float* __restrict__ z1, const float* __restrict__ z2,
                            int T, int lvl) {
    __shared__ float Zs[16][CDIM + 1];
    __shared__ float simS[16][17];
    __shared__ float red[24];
    int t = blockIdx.x;
    int tid = threadIdx.x;

    for (int e = tid; e < 16 * CDIM; e += 256) {
        int n = e / CDIM, c = e - n * CDIM;
        const float* src = (n < 8) ? z1 : z2;
        Zs[n][c] = src[((n & 7) * CDIM + c) * T + t];
    }
    __syncthreads();

    int n = tid >> 4, m = tid & 15;
    float acc = 0.f;
#pragma unroll 8
    for (int c = 0; c < CDIM; c++) acc = fmaf(Zs[n][c], Zs[m][c], acc);
    simS[n][m] = acc;
    __syncthreads();

    if (tid < 16) {
        float mx = -INFINITY;
#pragma unroll
        for (int j = 0; j < 16; j++) if (j != tid) mx = fmaxf(mx, simS[tid][j]);
        float s = 0.f;
#pragma unroll
        for (int j = 0; j < 16; j++) if (j != tid) s += __expf(simS[tid][j] - mx);
        red[tid] = mx + logf(s);
    }
    if (tid >= 16 && tid < 24) {
        int i = tid - 16;
        red[tid] = simS[i][8 + i];   // positive pair
    }
    __syncthreads();
    if (tid == 0) {
        float lsum = 0.f, psum = 0.f;
        for (int j = 0; j < 16; j++) lsum += red[j];
        for (int j = 16; j < 24; j++) psum += red[j];
        atomicAdd(&g_lse_i[lvl], (double)lsum);
        atomicAdd(&g_pos_i[lvl], (double)psum);
    }
}

// ---------------- temporal contrast: N=T, L=B=8 ----------------
// Per batch b: Z [M=2T, 320], rows t<T from z1[b,:,t], else z2[b,:,t-T].
// Flash-style: 128-row tile per block, stream 128-col tiles, fp32 GEMM
// (128x128x8 panels, 8x8 micro-tiles) + online logsumexp excluding diagonal.
__global__ void __launch_bounds__(256, 2)
temp_kernel(const float* __restrict__ z1, const float* __restrict__ z2, int T, int lvl) {
    __shared__ float As[8][128];
    __shared__ float Bs[8][128];
    __shared__ float m_run[128];
    __shared__ float s_run[128];
    __shared__ float redbuf[16];

    int b  = blockIdx.y;
    int M  = 2 * T;
    int r0 = blockIdx.x * 128;
    int tid = threadIdx.x;
    int ty = tid >> 4, tx = tid & 15;

    const float* z1b = z1 + b * CDIM * T;
    const float* z2b = z2 + b * CDIM * T;

    if (tid < 128) { m_run[tid] = -INFINITY; s_run[tid] = 0.f; }
    __syncthreads();

    float pos_acc = 0.f;
    int nct = (M + 127) >> 7;

    for (int ct = 0; ct < nct; ct++) {
        int c0 = ct << 7;
        float acc[8][8];
#pragma unroll
        for (int i = 0; i < 8; i++)
#pragma unroll
            for (int j = 0; j < 8; j++) acc[i][j] = 0.f;

        for (int kp = 0; kp < CDIM / 8; kp++) {
            int kc0 = kp * 8;
#pragma unroll
            for (int q = 0; q < 4; q++) {
                int e  = tid + (q << 8);
                int kk = e >> 7, rr = e & 127;
                int row = r0 + rr;
                float v = 0.f;
                if (row < M) v = (row < T) ? z1b[(kc0 + kk) * T + row]
                                           : z2b[(kc0 + kk) * T + row - T];
                As[kk][rr] = v;
                int col = c0 + rr;
                float w = 0.f;
                if (col < M) w = (col < T) ? z1b[(kc0 + kk) * T + col]
                                           : z2b[(kc0 + kk) * T + col - T];
                Bs[kk][rr] = w;
            }
            __syncthreads();
#pragma unroll
            for (int kk = 0; kk < 8; kk++) {
                float4 a0 = *(const float4*)&As[kk][ty << 3];
                float4 a1 = *(const float4*)&As[kk][(ty << 3) + 4];
                float4 b0 = *(const float4*)&Bs[kk][tx << 3];
                float4 b1 = *(const float4*)&Bs[kk][(tx << 3) + 4];
                float av[8] = {a0.x, a0.y, a0.z, a0.w, a1.x, a1.y, a1.z, a1.w};
                float bv[8] = {b0.x, b0.y, b0.z, b0.w, b1.x, b1.y, b1.z, b1.w};
#pragma unroll
                for (int i = 0; i < 8; i++)
#pragma unroll
                    for (int j = 0; j < 8; j++)
                        acc[i][j] = fmaf(av[i], bv[j], acc[i][j]);
            }
            __syncthreads();
        }

        // online softmax epilogue for this 128-col tile
#pragma unroll
        for (int i = 0; i < 8; i++) {
            int lr  = (ty << 3) + i;
            int row = r0 + lr;

            float tmax = -INFINITY;
#pragma unroll
            for (int j = 0; j < 8; j++) {
                int col = c0 + (tx << 3) + j;
                bool ok = (col < M) && (col != row);
                if (ok) tmax = fmaxf(tmax, acc[i][j]);
                if (row < T && col == row + T) pos_acc += acc[i][j];
            }
#pragma unroll
            for (int o = 8; o; o >>= 1)
                tmax = fmaxf(tmax, __shfl_xor_sync(0xffffffffu, tmax, o));

            float mold = m_run[lr];
            float newm = fmaxf(mold, tmax);

            float lsum = 0.f;
            if (newm > -INFINITY) {
#pragma unroll
                for (int j = 0; j < 8; j++) {
                    int col = c0 + (tx << 3) + j;
                    bool ok = (col < M) && (col != row);
                    if (ok) lsum += __expf(acc[i][j] - newm);
                }
            }
#pragma unroll
            for (int o = 8; o; o >>= 1)
                lsum += __shfl_xor_sync(0xffffffffu, lsum, o);

            if (tx == 0 && row < M && newm > -INFINITY) {
                s_run[lr] = s_run[lr] * __expf(mold - newm) + lsum;
                m_run[lr] = newm;
            }
        }
    }
    __syncthreads();

    // per-row LSE, then block reduction + atomics
    float lse = 0.f;
    if (tid < 128) {
        int row = r0 + tid;
        if (row < M) lse = m_run[tid] + logf(s_run[tid]);
    }
    float v1 = lse, v2 = pos_acc;
#pragma unroll
    for (int o = 16; o; o >>= 1) {
        v1 += __shfl_xor_sync(0xffffffffu, v1, o);
        v2 += __shfl_xor_sync(0xffffffffu, v2, o);
    }
    if ((tid & 31) == 0) {
        redbuf[tid >> 5]     = v1;
        redbuf[8 + (tid >> 5)] = v2;
    }
    __syncthreads();
    if (tid == 0) {
        float s1 = 0.f, s2 = 0.f;
        for (int w = 0; w < 8; w++) { s1 += redbuf[w]; s2 += redbuf[8 + w]; }
        atomicAdd(&g_lse_t[lvl], (double)s1);
        atomicAdd(&g_pos_t[lvl], (double)s2);
    }
}

// loss_dir(level) = lse_sum/(2*L*N) - pos_sum/(L*N); both directions have L*N = 8*T_k.
__global__ void finalize_kernel(float* out) {
    double inst = 0.0, temp = 0.0;
    for (int k = 0; k < NLEV; k++) {
        double Tk = (double)(T0 >> k);
        inst += g_lse_i[k] / (16.0 * Tk) - g_pos_i[k] / (8.0 * Tk);
        temp += g_lse_t[k] / (16.0 * Tk) - g_pos_t[k] / (8.0 * Tk);
    }
    inst /= NDIV;
    temp /= NDIV;
    out[0] = (float)(0.5 * (inst + temp));
    out[1] = (float)inst;
    out[2] = (float)temp;
}

extern "C" void kernel_launch(void* const* d_in, const int* in_sizes, int n_in,
                              void* d_out, int out_size) {
    const float* z1 = (const float*)d_in[0];
    const float* z2 = (const float*)d_in[1];
    float* out = (float*)d_out;

    float *p1, *p2;
    cudaGetSymbolAddress((void**)&p1, g_p1);
    cudaGetSymbolAddress((void**)&p2, g_p2);

    const float* l1[NLEV];
    const float* l2[NLEV];
    l1[0] = z1; l2[0] = z2;
    size_t off = 0;
    for (int k = 1; k < NLEV; k++) {
        int Tk = T0 >> k;
        l1[k] = p1 + off;
        l2[k] = p2 + off;
        off += (size_t)BDIM * CDIM * Tk;
    }

    init_acc<<<1, 32>>>();

    // build pyramids
    for (int k = 0; k < NLEV - 1; k++) {
        int Tin = T0 >> k;
        int n = BDIM * CDIM * (Tin >> 1);
        int blocks = (n + 255) / 256;
        if (blocks > 1184) blocks = 1184;
        pool_kernel<<<blocks, 256>>>(l1[k], (float*)l1[k + 1], Tin);
        pool_kernel<<<blocks, 256>>>(l2[k], (float*)l2[k + 1], Tin);
    }

    // per-level losses
    for (int k = 0; k < NLEV; k++) {
        int Tk = T0 >> k;
        inst_kernel<<<Tk, 256>>>(l1[k], l2[k], Tk, k);
        dim3 g((2 * Tk + 127) / 128, BDIM);
        temp_kernel<<<g, 256>>>(l1[k], l2[k], Tk, k);
    }

    finalize_kernel<<<1, 1>>>(out);
}

// round 2
// speedup vs baseline: 4.1849x; 4.1849x over previous
#include <cuda_runtime.h>
#include <cuda_bf16.h>
#include <math.h>
#include <stdint.h>

#define BDIM 8
#define CDIM 320
#define T0   2048
#define NLEV 12
#define NDIV 11.0

// fp32 pyramid for levels 1..11 (level 0 = harness input): sum T_k = 2047
__device__ float g_p1[BDIM * CDIM * 2047];
__device__ float g_p2[BDIM * CDIM * 2047];
// bf16 pyramid for ALL levels 0..11: sum T_k = 4095
__device__ __nv_bfloat16 g_b1[BDIM * CDIM * 4095];
__device__ __nv_bfloat16 g_b2[BDIM * CDIM * 4095];

__device__ double g_lse_i[NLEV], g_pos_i[NLEV], g_lse_t[NLEV], g_pos_t[NLEV];

__global__ void init_acc() {
    int i = threadIdx.x;
    if (i < NLEV) {
        g_lse_i[i] = 0.0; g_pos_i[i] = 0.0;
        g_lse_t[i] = 0.0; g_pos_t[i] = 0.0;
    }
}

// fp32 -> bf16 convert (level 0)
__global__ void cvt_kernel(const float* __restrict__ in, __nv_bfloat16* __restrict__ out, int n2) {
    // n2 = n/2, vectorized by 2
    for (int i = blockIdx.x * blockDim.x + threadIdx.x; i < n2; i += gridDim.x * blockDim.x) {
        float2 v = ((const float2*)in)[i];
        __nv_bfloat162 o;
        o.x = __float2bfloat16(v.x);
        o.y = __float2bfloat16(v.y);
        ((__nv_bfloat162*)out)[i] = o;
    }
}

// max-pool1d k=2 s=2 along T (fp32)
__global__ void pool_kernel(const float* __restrict__ in, float* __restrict__ out, int Tin) {
    int Tout = Tin >> 1;
    int n = BDIM * CDIM * Tout;
    for (int i = blockIdx.x * blockDim.x + threadIdx.x; i < n; i += gridDim.x * blockDim.x) {
        int bc = i / Tout;
        int t  = i - bc * Tout;
        const float* p = in + bc * Tin + 2 * t;
        out[i] = fmaxf(p[0], p[1]);
    }
}

// max-pool1d (bf16): max in fp32 then convert back (exact, values already bf16)
__global__ void poolb_kernel(const __nv_bfloat16* __restrict__ in, __nv_bfloat16* __restrict__ out, int Tin) {
    int Tout = Tin >> 1;
    int n = BDIM * CDIM * Tout;
    for (int i = blockIdx.x * blockDim.x + threadIdx.x; i < n; i += gridDim.x * blockDim.x) {
        int bc = i / Tout;
        int t  = i - bc * Tout;
        const __nv_bfloat16* p = in + bc * Tin + 2 * t;
        float a = __bfloat162float(p[0]), b = __bfloat162float(p[1]);
        out[i] = __float2bfloat16(fmaxf(a, b));
    }
}

// ---------------- instance contrast (fp32, cheap) ----------------
__global__ void inst_kernel(const float* __restrict__ z1, const float* __restrict__ z2,
                            int T, int lvl) {
    __shared__ float Zs[16][CDIM + 1];
    __shared__ float simS[16][17];
    __shared__ float red[24];
    int t = blockIdx.x;
    int tid = threadIdx.x;

    for (int e = tid; e < 16 * CDIM; e += 256) {
        int n = e / CDIM, c = e - n * CDIM;
        const float* src = (n < 8) ? z1 : z2;
        Zs[n][c] = src[((n & 7) * CDIM + c) * T + t];
    }
    __syncthreads();

    int n = tid >> 4, m = tid & 15;
    float acc = 0.f;
#pragma unroll 8
    for (int c = 0; c < CDIM; c++) acc = fmaf(Zs[n][c], Zs[m][c], acc);
    simS[n][m] = acc;
    __syncthreads();

    if (tid < 16) {
        float mx = -INFINITY;
#pragma unroll
        for (int j = 0; j < 16; j++) if (j != tid) mx = fmaxf(mx, simS[tid][j]);
        float s = 0.f;
#pragma unroll
        for (int j = 0; j < 16; j++) if (j != tid) s += __expf(simS[tid][j] - mx);
        red[tid] = mx + logf(s);
    }
    if (tid >= 16 && tid < 24) {
        int i = tid - 16;
        red[tid] = simS[i][8 + i];
    }
    __syncthreads();
    if (tid == 0) {
        float lsum = 0.f, psum = 0.f;
        for (int j = 0; j < 16; j++) lsum += red[j];
        for (int j = 16; j < 24; j++) psum += red[j];
        atomicAdd(&g_lse_i[lvl], (double)lsum);
        atomicAdd(&g_pos_i[lvl], (double)psum);
    }
}

// ---------------- temporal contrast via bf16 mma.sync ----------------

__device__ __forceinline__ uint32_t s2u(const void* p) {
    return (uint32_t)__cvta_generic_to_shared(p);
}

__device__ __forceinline__ void ldsm4t(uint32_t& r0, uint32_t& r1, uint32_t& r2, uint32_t& r3,
                                       uint32_t a) {
    asm volatile("ldmatrix.sync.aligned.m8n8.x4.trans.shared.b16 {%0,%1,%2,%3}, [%4];"
                 : "=r"(r0), "=r"(r1), "=r"(r2), "=r"(r3) : "r"(a));
}

__device__ __forceinline__ void mma16816(float* c, uint32_t a0, uint32_t a1, uint32_t a2,
                                         uint32_t a3, uint32_t b0, uint32_t b1) {
    asm volatile(
        "mma.sync.aligned.m16n8k16.row.col.f32.bf16.bf16.f32 "
        "{%0,%1,%2,%3},{%4,%5,%6,%7},{%8,%9},{%0,%1,%2,%3};"
        : "+f"(c[0]), "+f"(c[1]), "+f"(c[2]), "+f"(c[3])
        : "r"(a0), "r"(a1), "r"(a2), "r"(a3), "r"(b0), "r"(b1));
}

// consume one 32-deep K chunk from (bufA, bufB) smem (swizzled [k][idx] bf16, 256B rows)
__device__ __forceinline__ void consume_chunk(float acc[16][4], uint32_t baseA, uint32_t baseB,
                                              int mw, int li, int sel) {
#pragma unroll
    for (int ks = 0; ks < 32; ks += 16) {
        int rowkA = ks + ((sel >> 1) << 3) + li;
        uint32_t abyte = ((uint32_t)(2 * (mw + ((sel & 1) << 3)))) ^ (uint32_t)((rowkA & 7) << 4);
        uint32_t a0, a1, a2, a3;
        ldsm4t(a0, a1, a2, a3, baseA + (rowkA << 8) + abyte);

        int rowkB = ks + ((sel & 1) << 3) + li;
        uint32_t swb = (uint32_t)((rowkB & 7) << 4);
        uint32_t nsel = (uint32_t)((sel >> 1) << 4);
        uint32_t rowbB = baseB + (rowkB << 8);
#pragma unroll
        for (int p = 0; p < 8; p++) {
            uint32_t bb = (((uint32_t)(p << 5)) | nsel) ^ swb;
            uint32_t b0, b1, b2, b3;
            ldsm4t(b0, b1, b2, b3, rowbB + bb);
            mma16816(acc[2 * p], a0, a1, a2, a3, b0, b1);
            mma16816(acc[2 * p + 1], a0, a1, a2, a3, b2, b3);
        }
    }
}

__global__ void __launch_bounds__(256)
tempmma_kernel(const __nv_bfloat16* __restrict__ zb1, const __nv_bfloat16* __restrict__ zb2,
               int T, int lvl) {
    __shared__ __align__(16) unsigned char smA[2][8192];
    __shared__ __align__(16) unsigned char smB[2][8192];
    __shared__ float redbuf[16];

    int b = blockIdx.y;
    int M = 2 * T;
    int r0 = blockIdx.x * 128;
    int tid = threadIdx.x;
    int lane = tid & 31;
    int warp = tid >> 5;
    int mw = warp * 16;
    int gid = lane >> 2, tidq = lane & 3;
    int li = lane & 7, sel = lane >> 3;

    const __nv_bfloat16* z1b = zb1 + (size_t)b * CDIM * T;
    const __nv_bfloat16* z2b = zb2 + (size_t)b * CDIM * T;

    float mrun0 = -INFINITY, mrun1 = -INFINITY, srun0 = 0.f, srun1 = 0.f, pos = 0.f;
    int lrA = mw + gid, lrB = lrA + 8;

    uint32_t uA0 = s2u(smA[0]), uA1 = s2u(smA[1]);
    uint32_t uB0 = s2u(smB[0]), uB1 = s2u(smB[1]);

    if (T >= 128) {
        // ---- fast path: T multiple of 128, no padding/straddling ----
        const uint32_t* srcA = (const uint32_t*)((r0 < T) ? z1b : z2b);
        int rA0 = (r0 < T) ? r0 : r0 - T;
        int nct = M >> 7;

        for (int ct = 0; ct < nct; ct++) {
            int c0 = ct << 7;
            const uint32_t* srcB = (const uint32_t*)((c0 < T) ? z1b : z2b);
            int cB0 = (c0 < T) ? c0 : c0 - T;

            float acc[16][4];
#pragma unroll
            for (int q = 0; q < 16; q++)
#pragma unroll
                for (int j = 0; j < 4; j++) acc[q][j] = 0.f;

            uint32_t rA[8], rB[8];
            // preload chunk 0
#pragma unroll
            for (int it = 0; it < 8; it++) {
                int e = tid + (it << 8);
                int k = e >> 6, mp = e & 63;
                rA[it] = srcA[((k * T + rA0) >> 1) + mp];
                rB[it] = srcB[((k * T + cB0) >> 1) + mp];
            }
            // STS chunk 0 -> buf 0
#pragma unroll
            for (int it = 0; it < 8; it++) {
                int e = tid + (it << 8);
                int k = e >> 6, mp = e & 63;
                uint32_t boff = (k << 8) + (((uint32_t)(mp << 2)) ^ (uint32_t)((k & 7) << 4));
                *(uint32_t*)(&smA[0][boff]) = rA[it];
                *(uint32_t*)(&smB[0][boff]) = rB[it];
            }
            __syncthreads();

            for (int kc = 0; kc < 10; kc++) {
                if (kc < 9) {
                    int cb = (kc + 1) * 32;
#pragma unroll
                    for (int it = 0; it < 8; it++) {
                        int e = tid + (it << 8);
                        int k = e >> 6, mp = e & 63;
                        rA[it] = srcA[(((cb + k) * T + rA0) >> 1) + mp];
                        rB[it] = srcB[(((cb + k) * T + cB0) >> 1) + mp];
                    }
                }
                uint32_t bA = (kc & 1) ? uA1 : uA0;
                uint32_t bB = (kc & 1) ? uB1 : uB0;
                consume_chunk(acc, bA, bB, mw, li, sel);
                if (kc < 9) {
                    int bi = (kc + 1) & 1;
#pragma unroll
                    for (int it = 0; it < 8; it++) {
                        int e = tid + (it << 8);
                        int k = e >> 6, mp = e & 63;
                        uint32_t boff = (k << 8) + (((uint32_t)(mp << 2)) ^ (uint32_t)((k & 7) << 4));
                        *(uint32_t*)(&smA[bi][boff]) = rA[it];
                        *(uint32_t*)(&smB[bi][boff]) = rB[it];
                    }
                    __syncthreads();
                }
            }

            // ---- epilogue: online LSE for this 128-col tile ----
            bool diag = (c0 == r0);
            bool isP  = (c0 == r0 + T);
            float tm0 = -INFINITY, tm1 = -INFINITY;
#pragma unroll
            for (int nt = 0; nt < 16; nt++) {
#pragma unroll
                for (int j = 0; j < 2; j++) {
                    int lc = nt * 8 + 2 * tidq + j;
                    float v0 = acc[nt][j], v1 = acc[nt][2 + j];
                    if (isP) {
                        if (lc == lrA) pos += v0;
                        if (lc == lrB) pos += v1;
                    }
                    if (diag) {
                        if (lc == lrA) v0 = -INFINITY;
                        if (lc == lrB) v1 = -INFINITY;
                    }
                    acc[nt][j] = v0; acc[nt][2 + j] = v1;
                    tm0 = fmaxf(tm0, v0); tm1 = fmaxf(tm1, v1);
                }
            }
            tm0 = fmaxf(tm0, __shfl_xor_sync(0xffffffffu, tm0, 1));
            tm0 = fmaxf(tm0, __shfl_xor_sync(0xffffffffu, tm0, 2));
            tm1 = fmaxf(tm1, __shfl_xor_sync(0xffffffffu, tm1, 1));
            tm1 = fmaxf(tm1, __shfl_xor_sync(0xffffffffu, tm1, 2));
            float nm0 = fmaxf(mrun0, tm0), nm1 = fmaxf(mrun1, tm1);
            float s0 = 0.f, s1 = 0.f;
#pragma unroll
            for (int nt = 0; nt < 16; nt++) {
#pragma unroll
                for (int j = 0; j < 2; j++) {
                    s0 += __expf(acc[nt][j] - nm0);
                    s1 += __expf(acc[nt][2 + j] - nm1);
                }
            }
            s0 += __shfl_xor_sync(0xffffffffu, s0, 1);
            s0 += __shfl_xor_sync(0xffffffffu, s0, 2);
            s1 += __shfl_xor_sync(0xffffffffu, s1, 1);
            s1 += __shfl_xor_sync(0xffffffffu, s1, 2);
            float sc0 = (mrun0 == -INFINITY) ? 0.f : __expf(mrun0 - nm0);
            float sc1 = (mrun1 == -INFINITY) ? 0.f : __expf(mrun1 - nm1);
            srun0 = srun0 * sc0 + s0; mrun0 = nm0;
            srun1 = srun1 * sc1 + s1; mrun1 = nm1;
            __syncthreads();   // protect smem bufs before next ct reuses them
        }
    } else {
        // ---- slow path: M = 2T <= 128, single padded tile, B tile == A tile ----
        float acc[16][4];
#pragma unroll
        for (int q = 0; q < 16; q++)
#pragma unroll
            for (int j = 0; j < 4; j++) acc[q][j] = 0.f;

        for (int kc = 0; kc < 10; kc++) {
            __syncthreads();
#pragma unroll
            for (int it = 0; it < 16; it++) {
                int e = tid + (it << 8);
                int k = e >> 7, m = e & 127;
                int c = kc * 32 + k;
                unsigned short v = 0;
                if (m < T)      v = *(const unsigned short*)&z1b[c * T + m];
                else if (m < M) v = *(const unsigned short*)&z2b[c * T + m - T];
                *(unsigned short*)(&smA[0][(k << 8) + (((uint32_t)(2 * m)) ^ (uint32_t)((k & 7) << 4))]) = v;
            }
            __syncthreads();
            consume_chunk(acc, uA0, uA0, mw, li, sel);
        }

        float tm0 = -INFINITY, tm1 = -INFINITY;
#pragma unroll
        for (int nt = 0; nt < 16; nt++) {
#pragma unroll
            for (int j = 0; j < 2; j++) {
                int lc = nt * 8 + 2 * tidq + j;
                float v0 = acc[nt][j], v1 = acc[nt][2 + j];
                if (lrA < T && lc == lrA + T) pos += v0;
                if (lrB < T && lc == lrB + T) pos += v1;
                if (lc >= M || lc == lrA) v0 = -INFINITY;
                if (lc >= M || lc == lrB) v1 = -INFINITY;
                acc[nt][j] = v0; acc[nt][2 + j] = v1;
                tm0 = fmaxf(tm0, v0); tm1 = fmaxf(tm1, v1);
            }
        }
        tm0 = fmaxf(tm0, __shfl_xor_sync(0xffffffffu, tm0, 1));
        tm0 = fmaxf(tm0, __shfl_xor_sync(0xffffffffu, tm0, 2));
        tm1 = fmaxf(tm1, __shfl_xor_sync(0xffffffffu, tm1, 1));
        tm1 = fmaxf(tm1, __shfl_xor_sync(0xffffffffu, tm1, 2));
        float nm0 = fmaxf(mrun0, tm0), nm1 = fmaxf(mrun1, tm1);
        float s0 = 0.f, s1 = 0.f;
#pragma unroll
        for (int nt = 0; nt < 16; nt++) {
#pragma unroll
            for (int j = 0; j < 2; j++) {
                if (nm0 != -INFINITY) s0 += __expf(acc[nt][j] - nm0);
                if (nm1 != -INFINITY) s1 += __expf(acc[nt][2 + j] - nm1);
            }
        }
        s0 += __shfl_xor_sync(0xffffffffu, s0, 1);
        s0 += __shfl_xor_sync(0xffffffffu, s0, 2);
        s1 += __shfl_xor_sync(0xffffffffu, s1, 1);
        s1 += __shfl_xor_sync(0xffffffffu, s1, 2);
        if (nm0 != -INFINITY) { srun0 = s0; mrun0 = nm0; }
        if (nm1 != -INFINITY) { srun1 = s1; mrun1 = nm1; }
    }

    // ---- final reduction ----
    float lsum = 0.f;
    if (tidq == 0) {
        int gr0 = r0 + lrA, gr1 = r0 + lrB;
        if (gr0 < M && srun0 > 0.f) lsum += mrun0 + logf(srun0);
        if (gr1 < M && srun1 > 0.f) lsum += mrun1 + logf(srun1);
    }
    float psum = pos;
#pragma unroll
    for (int o = 16; o; o >>= 1) {
        lsum += __shfl_xor_sync(0xffffffffu, lsum, o);
        psum += __shfl_xor_sync(0xffffffffu, psum, o);
    }
    if (lane == 0) {
        redbuf[warp] = lsum;
        redbuf[8 + warp] = psum;
    }
    __syncthreads();
    if (tid == 0) {
        float a = 0.f, p2 = 0.f;
        for (int w = 0; w < 8; w++) { a += redbuf[w]; p2 += redbuf[8 + w]; }
        atomicAdd(&g_lse_t[lvl], (double)a);
        atomicAdd(&g_pos_t[lvl], (double)p2);
    }
}

__global__ void finalize_kernel(float* out) {
    double inst = 0.0, temp = 0.0;
    for (int k = 0; k < NLEV; k++) {
        double Tk = (double)(T0 >> k);
        inst += g_lse_i[k] / (16.0 * Tk) - g_pos_i[k] / (8.0 * Tk);
        temp += g_lse_t[k] / (16.0 * Tk) - g_pos_t[k] / (8.0 * Tk);
    }
    inst /= NDIV;
    temp /= NDIV;
    out[0] = (float)(0.5 * (inst + temp));
    out[1] = (float)inst;
    out[2] = (float)temp;
}

extern "C" void kernel_launch(void* const* d_in, const int* in_sizes, int n_in,
                              void* d_out, int out_size) {
    const float* z1 = (const float*)d_in[0];
    const float* z2 = (const float*)d_in[1];
    float* out = (float*)d_out;

    float *p1, *p2;
    __nv_bfloat16 *b1, *b2;
    cudaGetSymbolAddress((void**)&p1, g_p1);
    cudaGetSymbolAddress((void**)&p2, g_p2);
    cudaGetSymbolAddress((void**)&b1, g_b1);
    cudaGetSymbolAddress((void**)&b2, g_b2);

    const float* l1[NLEV];
    const float* l2[NLEV];
    __nv_bfloat16* lb1[NLEV];
    __nv_bfloat16* lb2[NLEV];
    l1[0] = z1; l2[0] = z2;
    size_t offf = 0, offb = 0;
    for (int k = 0; k < NLEV; k++) {
        int Tk = T0 >> k;
        lb1[k] = b1 + offb;
        lb2[k] = b2 + offb;
        offb += (size_t)BDIM * CDIM * Tk;
        if (k >= 1) {
            l1[k] = p1 + offf;
            l2[k] = p2 + offf;
            offf += (size_t)BDIM * CDIM * Tk;
        }
    }

    init_acc<<<1, 32>>>();

    // level-0 bf16 conversion
    {
        int n2 = BDIM * CDIM * T0 / 2;
        int blocks = (n2 + 255) / 256;
        if (blocks > 1184) blocks = 1184;
        cvt_kernel<<<blocks, 256>>>(z1, lb1[0], n2);
        cvt_kernel<<<blocks, 256>>>(z2, lb2[0], n2);
    }

    // pyramids: fp32 (for inst) + bf16 (for temp)
    for (int k = 0; k < NLEV - 1; k++) {
        int Tin = T0 >> k;
        int n = BDIM * CDIM * (Tin >> 1);
        int blocks = (n + 255) / 256;
        if (blocks > 1184) blocks = 1184;
        pool_kernel<<<blocks, 256>>>(l1[k], (float*)l1[k + 1], Tin);
        pool_kernel<<<blocks, 256>>>(l2[k], (float*)l2[k + 1], Tin);
        poolb_kernel<<<blocks, 256>>>(lb1[k], lb1[k + 1], Tin);
        poolb_kernel<<<blocks, 256>>>(lb2[k], lb2[k + 1], Tin);
    }

    for (int k = 0; k < NLEV; k++) {
        int Tk = T0 >> k;
        inst_kernel<<<Tk, 256>>>(l1[k], l2[k], Tk, k);
        int rb = (Tk >= 128) ? ((2 * Tk) >> 7) : 1;
        dim3 g(rb, BDIM);
        tempmma_kernel<<<g, 256>>>(lb1[k], lb2[k], Tk, k);
    }

    finalize_kernel<<<1, 1>>>(out);
}

// round 3
// speedup vs baseline: 11.0736x; 2.6461x over previous
#include <cuda_runtime.h>
#include <cuda_bf16.h>
#include <math.h>
#include <stdint.h>

#define CDIM 320
#define T0   2048
#define NLEV 12
#define NDIV 11.0

// fp32 pyramid levels 1..11 (level 0 = harness input)
__device__ __align__(16) float g_p1[8 * CDIM * 2047];
__device__ __align__(16) float g_p2[8 * CDIM * 2047];
// bf16 pyramid levels 0..11
__device__ __align__(16) __nv_bfloat16 g_b1[8 * CDIM * 4095];
__device__ __align__(16) __nv_bfloat16 g_b2[8 * CDIM * 4095];
// level-0 col-split partial stats: [half][b*4096 + row]
__device__ float g_pm[2][32768];
__device__ float g_ps[2][32768];

__device__ double g_lse_i[NLEV], g_pos_i[NLEV], g_lse_t[NLEV], g_pos_t[NLEV];

__constant__ int c_T[12]      = {2048,1024,512,256,128,64,32,16,8,4,2,1};
__constant__ int c_offb[12]   = {0,5242880,7864320,9175040,9830400,10158080,10321920,10403840,10444800,10465280,10475520,10480640};
__constant__ int c_offf[12]   = {0,0,2621440,3932160,4587520,4915200,5079040,5160960,5201920,5222400,5232640,5237760};
__constant__ int c_tstart[12] = {0,2048,3072,3584,3840,3968,4032,4064,4080,4088,4092,4094};
__constant__ int c_bstart[12] = {0,512,640,704,736,752,760,768,776,784,792,800};

__global__ void init_acc() {
    int i = threadIdx.x;
    if (i < NLEV) {
        g_lse_i[i] = 0.0; g_pos_i[i] = 0.0;
        g_lse_t[i] = 0.0; g_pos_t[i] = 0.0;
    }
}

// ---------------- one-shot pyramid: all pool levels, fp32 + bf16 ----------------
__global__ void pyramid_kernel(const float* __restrict__ z1, const float* __restrict__ z2) {
    __shared__ float s[3072];
    int bc = blockIdx.x;                 // 0..2559 = b*320 + c
    int y  = blockIdx.y;
    const float* src = (y ? z2 : z1) + (size_t)bc * T0;
    float* pf = y ? g_p2 : g_p1;
    __nv_bfloat16* pb = y ? g_b2 : g_b1;
    int tid = threadIdx.x;               // 256

    __nv_bfloat162* pb0 = (__nv_bfloat162*)(pb + (size_t)bc * T0);
    for (int i = tid; i < 512; i += 256) {
        float4 v = ((const float4*)src)[i];
        ((float4*)s)[i] = v;
        __nv_bfloat162 o1, o2;
        o1.x = __float2bfloat16(v.x); o1.y = __float2bfloat16(v.y);
        o2.x = __float2bfloat16(v.z); o2.y = __float2bfloat16(v.w);
        pb0[2 * i]     = o1;
        pb0[2 * i + 1] = o2;
    }
    __syncthreads();

    float* cur = s;
    float* nxt = s + 2048;
    for (int k = 1; k < 12; k++) {
        int Tk = T0 >> k;
        for (int i = tid; i < Tk; i += 256) {
            float v = fmaxf(cur[2 * i], cur[2 * i + 1]);
            nxt[i] = v;
            pf[c_offf[k] + (size_t)bc * Tk + i] = v;
            pb[c_offb[k] + (size_t)bc * Tk + i] = __float2bfloat16(v);
        }
        __syncthreads();
        float* tmp = cur; cur = nxt; nxt = tmp;
    }
}

// ---------------- instance contrast, all levels fused ----------------
__global__ void inst_all(const float* __restrict__ z1, const float* __restrict__ z2) {
    __shared__ float Zs[16][CDIM + 1];
    __shared__ float simS[16][17];
    __shared__ float red[24];
    int bid = blockIdx.x;
    int lvl = 0;
#pragma unroll
    for (int k = 1; k < 12; k++) if (bid >= c_tstart[k]) lvl = k;
    int T = c_T[lvl];
    int t = bid - c_tstart[lvl];
    const float* s1 = lvl ? (g_p1 + c_offf[lvl]) : z1;
    const float* s2 = lvl ? (g_p2 + c_offf[lvl]) : z2;
    int tid = threadIdx.x;

    for (int e = tid; e < 16 * CDIM; e += 256) {
        int n = e / CDIM, c = e - n * CDIM;
        const float* src = (n < 8) ? s1 : s2;
        Zs[n][c] = src[((size_t)(n & 7) * CDIM + c) * T + t];
    }
    __syncthreads();

    int n = tid >> 4, m = tid & 15;
    float acc = 0.f;
#pragma unroll 8
    for (int c = 0; c < CDIM; c++) acc = fmaf(Zs[n][c], Zs[m][c], acc);
    simS[n][m] = acc;
    __syncthreads();

    if (tid < 16) {
        float mx = -INFINITY;
#pragma unroll
        for (int j = 0; j < 16; j++) if (j != tid) mx = fmaxf(mx, simS[tid][j]);
        float s = 0.f;
#pragma unroll
        for (int j = 0; j < 16; j++) if (j != tid) s += __expf(simS[tid][j] - mx);
        red[tid] = mx + logf(s);
    }
    if (tid >= 16 && tid < 24) {
        int i = tid - 16;
        red[tid] = simS[i][8 + i];
    }
    __syncthreads();
    if (tid == 0) {
        float lsum = 0.f, psum = 0.f;
        for (int j = 0; j < 16; j++) lsum += red[j];
        for (int j = 16; j < 24; j++) psum += red[j];
        atomicAdd(&g_lse_i[lvl], (double)lsum);
        atomicAdd(&g_pos_i[lvl], (double)psum);
    }
}

// ---------------- temporal contrast: bf16 HMMA, A-resident, cp.async ----------------

__device__ __forceinline__ uint32_t s2u(const void* p) {
    return (uint32_t)__cvta_generic_to_shared(p);
}
__device__ __forceinline__ void ldsm4t(uint32_t& r0, uint32_t& r1, uint32_t& r2, uint32_t& r3,
                                       uint32_t a) {
    asm volatile("ldmatrix.sync.aligned.m8n8.x4.trans.shared.b16 {%0,%1,%2,%3}, [%4];"
                 : "=r"(r0), "=r"(r1), "=r"(r2), "=r"(r3) : "r"(a));
}
__device__ __forceinline__ void mma16816(float* c, uint32_t a0, uint32_t a1, uint32_t a2,
                                         uint32_t a3, uint32_t b0, uint32_t b1) {
    asm volatile(
        "mma.sync.aligned.m16n8k16.row.col.f32.bf16.bf16.f32 "
        "{%0,%1,%2,%3},{%4,%5,%6,%7},{%8,%9},{%0,%1,%2,%3};"
        : "+f"(c[0]), "+f"(c[1]), "+f"(c[2]), "+f"(c[3])
        : "r"(a0), "r"(a1), "r"(a2), "r"(a3), "r"(b0), "r"(b1));
}
__device__ __forceinline__ void cpa16(uint32_t d, const void* s) {
    asm volatile("cp.async.cg.shared.global [%0], [%1], 16;" :: "r"(d), "l"(s));
}

// warp tile 32 rows x 128 cols; one 32-deep K chunk
__device__ __forceinline__ void consume32(float acc[2][16][4], uint32_t uA, int kbase,
                                          uint32_t baseB, int mw, int li, int sel) {
#pragma unroll
    for (int ks = 0; ks < 32; ks += 16) {
        int rowkA = kbase + ks + ((sel >> 1) << 3) + li;
        uint32_t sw = (uint32_t)((rowkA & 7) << 4);
        uint32_t a[2][4];
#pragma unroll
        for (int rb = 0; rb < 2; rb++) {
            uint32_t abyte = ((uint32_t)(2 * (mw + (rb << 4) + ((sel & 1) << 3)))) ^ sw;
            ldsm4t(a[rb][0], a[rb][1], a[rb][2], a[rb][3], uA + (rowkA << 8) + abyte);
        }
        int rowkB = ks + ((sel & 1) << 3) + li;
        uint32_t swb = (uint32_t)((rowkB & 7) << 4);
        uint32_t nsel = (uint32_t)((sel >> 1) << 4);
        uint32_t rowbB = baseB + (rowkB << 8);
#pragma unroll
        for (int p = 0; p < 8; p++) {
            uint32_t bb = (((uint32_t)(p << 5)) | nsel) ^ swb;
            uint32_t b0, b1, b2, b3;
            ldsm4t(b0, b1, b2, b3, rowbB + bb);
#pragma unroll
            for (int rb = 0; rb < 2; rb++) {
                mma16816(acc[rb][2 * p],     a[rb][0], a[rb][1], a[rb][2], a[rb][3], b0, b1);
                mma16816(acc[rb][2 * p + 1], a[rb][0], a[rb][1], a[rb][2], a[rb][3], b2, b3);
            }
        }
    }
}

#define SM_A_BYTES 81920
#define SM_B_BYTES 8192
#define SM_DYN (SM_A_BYTES + 3 * SM_B_BYTES + 32)

__global__ void __launch_bounds__(128)
temp_all() {
    extern __shared__ __align__(16) unsigned char sm[];
    uint32_t uA = s2u(sm);
    uint32_t uB0 = uA + SM_A_BYTES;
    uint32_t uB1 = uB0 + SM_B_BYTES;
    uint32_t uB2 = uB1 + SM_B_BYTES;
    float* redbuf = (float*)(sm + SM_A_BYTES + 3 * SM_B_BYTES);

    int bid = blockIdx.x;
    int lvl = 0;
#pragma unroll
    for (int k = 1; k < 12; k++) if (bid >= c_bstart[k]) lvl = k;
    int T = c_T[lvl];
    int local = bid - c_bstart[lvl];
    const __nv_bfloat16* zl1 = g_b1 + c_offb[lvl];
    const __nv_bfloat16* zl2 = g_b2 + c_offb[lvl];

    int tid = threadIdx.x, lane = tid & 31, warp = tid >> 5;
    int mw = warp << 5;
    int gid = lane >> 2, tidq = lane & 3;
    int li = lane & 7, sel = lane >> 3;

    float mrun[4] = {-INFINITY, -INFINITY, -INFINITY, -INFINITY};
    float srun[4] = {0.f, 0.f, 0.f, 0.f};
    float pos = 0.f;

    int b, r0, ct0, nct, half = 0;
    bool fast = (T >= 128);
    if (lvl == 0) {
        b = local >> 6;
        int rem = local & 63;
        r0 = (rem >> 1) << 7;
        half = rem & 1;
        ct0 = half << 4;
        nct = 16;
    } else if (fast) {
        int rbc = T >> 6;
        b = local / rbc;
        r0 = (local - b * rbc) << 7;
        ct0 = 0;
        nct = (2 * T) >> 7;
    } else {
        b = local; r0 = 0; ct0 = 0; nct = 1;
    }

    const __nv_bfloat16* z1b = zl1 + (size_t)b * CDIM * T;
    const __nv_bfloat16* z2b = zl2 + (size_t)b * CDIM * T;
    int M = 2 * T;

    if (fast) {
        const char* srcA = (const char*)((r0 < T) ? z1b : z2b);
        int rA0 = (r0 < T) ? r0 : r0 - T;
        // load full A tile [K=320][128 rows] once
#pragma unroll 4
        for (int i = tid; i < 5120; i += 128) {
            int k = i >> 4, c = i & 15;
            uint32_t dst = uA + (k << 8) + (((uint32_t)(c << 4)) ^ (uint32_t)((k & 7) << 4));
            cpa16(dst, srcA + ((size_t)k * T + rA0) * 2 + (c << 4));
        }
        asm volatile("cp.async.commit_group;" ::: "memory");

        for (int ci = 0; ci < nct; ci++) {
            int c0 = (ct0 + ci) << 7;
            const char* srcB = (const char*)((c0 < T) ? z1b : z2b);
            int cB0 = (c0 < T) ? c0 : c0 - T;

            // prefetch chunks 0 and 1
#pragma unroll
            for (int pc = 0; pc < 2; pc++) {
                uint32_t bu = pc ? uB1 : uB0;
#pragma unroll
                for (int i = tid; i < 512; i += 128) {
                    int k = i >> 4, c = i & 15;
                    uint32_t dst = bu + (k << 8) + (((uint32_t)(c << 4)) ^ (uint32_t)((k & 7) << 4));
                    cpa16(dst, srcB + ((size_t)(pc * 32 + k) * T + cB0) * 2 + (c << 4));
                }
                asm volatile("cp.async.commit_group;" ::: "memory");
            }

            float acc[2][16][4];
#pragma unroll
            for (int q = 0; q < 2; q++)
#pragma unroll
                for (int nt = 0; nt < 16; nt++)
#pragma unroll
                    for (int j = 0; j < 4; j++) acc[q][nt][j] = 0.f;

#pragma unroll 1
            for (int kc = 0; kc < 10; kc++) {
                if (kc < 9) asm volatile("cp.async.wait_group 1;" ::: "memory");
                else        asm volatile("cp.async.wait_group 0;" ::: "memory");
                __syncthreads();
                int r = kc % 3;
                uint32_t bu = (r == 0) ? uB0 : (r == 1) ? uB1 : uB2;
                consume32(acc, uA, kc * 32, bu, mw, li, sel);
                if (kc < 8) {
                    int tc = kc + 2;
                    int r2 = tc % 3;
                    uint32_t pu = (r2 == 0) ? uB0 : (r2 == 1) ? uB1 : uB2;
#pragma unroll
                    for (int i = tid; i < 512; i += 128) {
                        int k = i >> 4, c = i & 15;
                        uint32_t dst = pu + (k << 8) + (((uint32_t)(c << 4)) ^ (uint32_t)((k & 7) << 4));
                        cpa16(dst, srcB + ((size_t)(tc * 32 + k) * T + cB0) * 2 + (c << 4));
                    }
                    asm volatile("cp.async.commit_group;" ::: "memory");
                }
            }

            // online-LSE epilogue for this 128-col tile
            bool diag = (c0 == r0);
            bool isP  = (c0 == r0 + T);
#pragma unroll
            for (int rb = 0; rb < 2; rb++)
#pragma unroll
            for (int h = 0; h < 2; h++) {
                int e = 2 * rb + h;
                int lr = mw + (rb << 4) + (h << 3) + gid;
                float tm = -INFINITY;
#pragma unroll
                for (int nt = 0; nt < 16; nt++)
#pragma unroll
                for (int j = 0; j < 2; j++) {
                    int lc = (nt << 3) + (tidq << 1) + j;
                    float v = acc[rb][nt][(h << 1) + j];
                    if (isP && lc == lr) pos += v;
                    if (diag && lc == lr) v = -INFINITY;
                    acc[rb][nt][(h << 1) + j] = v;
                    tm = fmaxf(tm, v);
                }
                tm = fmaxf(tm, __shfl_xor_sync(0xffffffffu, tm, 1));
                tm = fmaxf(tm, __shfl_xor_sync(0xffffffffu, tm, 2));
                float nm = fmaxf(mrun[e], tm);
                float s = 0.f;
#pragma unroll
                for (int nt = 0; nt < 16; nt++)
#pragma unroll
                for (int j = 0; j < 2; j++)
                    s += __expf(acc[rb][nt][(h << 1) + j] - nm);
                s += __shfl_xor_sync(0xffffffffu, s, 1);
                s += __shfl_xor_sync(0xffffffffu, s, 2);
                float sc = (mrun[e] == -INFINITY) ? 0.f : __expf(mrun[e] - nm);
                srun[e] = srun[e] * sc + s;
                mrun[e] = nm;
            }
            __syncthreads();
        }
    } else {
        // ---- slow path: M = 2T <= 128, single padded tile, B == A ----
#pragma unroll 1
        for (int i = tid; i < 320 * 128; i += 128) {
            int k = i >> 7, m = i & 127;
            unsigned short v = 0;
            if (m < T)      v = *(const unsigned short*)(z1b + (size_t)k * T + m);
            else if (m < M) v = *(const unsigned short*)(z2b + (size_t)k * T + (m - T));
            *(unsigned short*)(sm + (k << 8) + (((uint32_t)(m << 1)) ^ (uint32_t)((k & 7) << 4))) = v;
        }
        __syncthreads();

        float acc[2][16][4];
#pragma unroll
        for (int q = 0; q < 2; q++)
#pragma unroll
            for (int nt = 0; nt < 16; nt++)
#pragma unroll
                for (int j = 0; j < 4; j++) acc[q][nt][j] = 0.f;

#pragma unroll 1
        for (int kc = 0; kc < 10; kc++)
            consume32(acc, uA, kc * 32, uA + (uint32_t)((kc * 32) << 8), mw, li, sel);

#pragma unroll
        for (int rb = 0; rb < 2; rb++)
#pragma unroll
        for (int h = 0; h < 2; h++) {
            int e = 2 * rb + h;
            int lr = mw + (rb << 4) + (h << 3) + gid;
            float tm = -INFINITY;
#pragma unroll
            for (int nt = 0; nt < 16; nt++)
#pragma unroll
            for (int j = 0; j < 2; j++) {
                int lc = (nt << 3) + (tidq << 1) + j;
                float v = acc[rb][nt][(h << 1) + j];
                if (lr < T && lc == lr + T) pos += v;
                if (lc >= M || lc == lr) v = -INFINITY;
                acc[rb][nt][(h << 1) + j] = v;
                tm = fmaxf(tm, v);
            }
            tm = fmaxf(tm, __shfl_xor_sync(0xffffffffu, tm, 1));
            tm = fmaxf(tm, __shfl_xor_sync(0xffffffffu, tm, 2));
            float s = 0.f;
            if (tm > -INFINITY) {
#pragma unroll
                for (int nt = 0; nt < 16; nt++)
#pragma unroll
                for (int j = 0; j < 2; j++)
                    s += __expf(acc[rb][nt][(h << 1) + j] - tm);
            }
            s += __shfl_xor_sync(0xffffffffu, s, 1);
            s += __shfl_xor_sync(0xffffffffu, s, 2);
            srun[e] = s;
            mrun[e] = tm;
        }
    }

    // ---- output ----
    if (lvl == 0) {
        if (tidq == 0) {
#pragma unroll
            for (int e = 0; e < 4; e++) {
                int lr = mw + ((e >> 1) << 4) + ((e & 1) << 3) + gid;
                int idx = (b << 12) + r0 + lr;
                g_pm[half][idx] = mrun[e];
                g_ps[half][idx] = srun[e];
            }
        }
        float ps = pos;
#pragma unroll
        for (int o = 16; o; o >>= 1) ps += __shfl_xor_sync(0xffffffffu, ps, o);
        if (lane == 0) redbuf[warp] = ps;
        __syncthreads();
        if (tid == 0) {
            float p2 = redbuf[0] + redbuf[1] + redbuf[2] + redbuf[3];
            atomicAdd(&g_pos_t[0], (double)p2);
        }
    } else {
        float lsum = 0.f;
        if (tidq == 0) {
#pragma unroll
            for (int e = 0; e < 4; e++) {
                int lr = mw + ((e >> 1) << 4) + ((e & 1) << 3) + gid;
                int row = r0 + lr;
                if (row < M && srun[e] > 0.f) lsum += mrun[e] + logf(srun[e]);
            }
        }
        float ps = pos;
#pragma unroll
        for (int o = 16; o; o >>= 1) {
            lsum += __shfl_xor_sync(0xffffffffu, lsum, o);
            ps   += __shfl_xor_sync(0xffffffffu, ps, o);
        }
        if (lane == 0) { redbuf[warp] = lsum; redbuf[4 + warp] = ps; }
        __syncthreads();
        if (tid == 0) {
            float a = redbuf[0] + redbuf[1] + redbuf[2] + redbuf[3];
            float p2 = redbuf[4] + redbuf[5] + redbuf[6] + redbuf[7];
            atomicAdd(&g_lse_t[lvl], (double)a);
            atomicAdd(&g_pos_t[lvl], (double)p2);
        }
    }
}

// merge the two level-0 col-halves per row, sum LSE into g_lse_t[0]
__global__ void lsered_kernel() {
    __shared__ float rb[8];
    int i = blockIdx.x * 256 + threadIdx.x;   // 32768 rows
    float m0 = g_pm[0][i], m1 = g_pm[1][i];
    float s0 = g_ps[0][i], s1 = g_ps[1][i];
    float m = fmaxf(m0, m1);
    float v = m + logf(s0 * __expf(m0 - m) + s1 * __expf(m1 - m));
#pragma unroll
    for (int o = 16; o; o >>= 1) v += __shfl_xor_sync(0xffffffffu, v, o);
    if ((threadIdx.x & 31) == 0) rb[threadIdx.x >> 5] = v;
    __syncthreads();
    if (threadIdx.x == 0) {
        float s = 0.f;
        for (int w = 0; w < 8; w++) s += rb[w];
        atomicAdd(&g_lse_t[0], (double)s);
    }
}

__global__ void finalize_kernel(float* out) {
    double inst = 0.0, temp = 0.0;
    for (int k = 0; k < NLEV; k++) {
        double Tk = (double)(T0 >> k);
        inst += g_lse_i[k] / (16.0 * Tk) - g_pos_i[k] / (8.0 * Tk);
        temp += g_lse_t[k] / (16.0 * Tk) - g_pos_t[k] / (8.0 * Tk);
    }
    inst /= NDIV;
    temp /= NDIV;
    out[0] = (float)(0.5 * (inst + temp));
    out[1] = (float)inst;
    out[2] = (float)temp;
}

extern "C" void kernel_launch(void* const* d_in, const int* in_sizes, int n_in,
                              void* d_out, int out_size) {
    const float* z1 = (const float*)d_in[0];
    const float* z2 = (const float*)d_in[1];
    float* out = (float*)d_out;

    cudaFuncSetAttribute(temp_all, cudaFuncAttributeMaxDynamicSharedMemorySize, SM_DYN);

    init_acc<<<1, 32>>>();
    dim3 pg(2560, 2);
    pyramid_kernel<<<pg, 256>>>(z1, z2);
    inst_all<<<4095, 256>>>(z1, z2);
    temp_all<<<808, 128, SM_DYN>>>();
    lsered_kernel<<<128, 256>>>();
    finalize_kernel<<<1, 1>>>(out);
}